// round 16
// baseline (speedup 1.0000x reference)
#include <cuda_runtime.h>
#include <cstdint>
#include <cstddef>

#define BB 512
#define NT 256
#define GRID 608      // 4 blocks/SM x 152 SMs, single wave
#define NTILE 16384   // 128 j-tiles (4 j) x 128 i-splits (4 i)
// smem: [0,2048) cls | [2048,34816) F1 staging 32KB | [34816,51200) 2-stage pipe 16KB
#define STG_OFF 2048
#define PIPE_OFF 34816
#define SMEM_BYTES 51200

typedef unsigned long long ull;

// Face accumulators {E,S}; .bss zero at load, finalize re-zeroes after reading.
__device__ float4 gF0[BB * BB / 2];  // [j*B+k]: sum over i
__device__ float4 gF1[BB * BB / 2];  // [i*B+k]: sum over j
__device__ float4 gF2[BB * BB / 2];  // [i*B+j]: sum over k

__device__ __forceinline__ void redAdd4(float4* p, float a, float b, float c, float d) {
    asm volatile("red.global.add.v4.f32 [%0], {%1, %2, %3, %4};"
                 :: "l"(p), "f"(a), "f"(b), "f"(c), "f"(d));
}
__device__ __forceinline__ ull pk2(float lo, float hi) {
    ull r; asm("mov.b64 %0, {%1, %2};" : "=l"(r) : "f"(lo), "f"(hi)); return r;
}
__device__ __forceinline__ void fadd2(ull& a, ull b) {
    asm("add.rn.f32x2 %0, %0, %1;" : "+l"(a) : "l"(b));
}
__device__ __forceinline__ float lo2(ull a) {
    float f; asm("{.reg .f32 h; mov.b64 {%0, h}, %1;}" : "=f"(f) : "l"(a)); return f;
}
__device__ __forceinline__ float hi2(ull a) {
    float f; asm("{.reg .f32 l; mov.b64 {l, %0}, %1;}" : "=f"(f) : "l"(a)); return f;
}
__device__ __forceinline__ void cpa16(unsigned dst, const void* src) {
    asm volatile("cp.async.cg.shared.global [%0], [%1], 16;"
                 :: "r"(dst), "l"(src));
}

#define ROW(vq, cjv, jj) { \
    const float fij = ((cjv) == ci) ? 1.f : 0.f; \
    float e0 = __expf(vq.x), e1 = __expf(vq.y), e2 = __expf(vq.z), e3 = __expf(vq.w); \
    ull t0 = pk2(e0, fij * vq.x), t1 = pk2(e1, fij * vq.y); \
    ull t2 = pk2(e2, fij * vq.z), t3 = pk2(e3, fij * vq.w); \
    fadd2(a0[(jj)*4+0], t0); fadd2(a0[(jj)*4+1], t1); \
    fadd2(a0[(jj)*4+2], t2); fadd2(a0[(jj)*4+3], t3); \
    fadd2(f1q0, t0); fadd2(f1q1, t1); fadd2(f1q2, t2); fadd2(f1q3, t3); \
    float sv  = (vq.x + vq.y) + (vq.z + vq.w); \
    float rs1 = vq.x * w1q0 + vq.y * w1q1 + vq.z * w1q2 + vq.w * w1q3; \
    vv[2 + (jj)] = ci ? rs1 : (sv - rs1); \
    vv[(jj)] = (e0 + e1) + (e2 + e3); }

__global__ __launch_bounds__(NT, 4) void main_kernel(const float* __restrict__ x,
                                                     const float* __restrict__ target,
                                                     float* __restrict__ out) {
    const int tid  = threadIdx.x;
    const int lane = tid & 31;
    const int w    = tid >> 5;       // 0..7
    const int jgrp = w >> 2;         // 0..1 : which 2-j group
    const int wk   = w & 3;          // 0..3 : 128-k segment
    const int kb   = wk * 128 + lane * 4;
    const unsigned FULL = 0xffffffffu;

    extern __shared__ char smem[];
    int* scls = reinterpret_cast<int*>(smem);
    ull* sF1  = reinterpret_cast<ull*>(smem + STG_OFF);
    const unsigned pipe_wr =
        (unsigned)__cvta_generic_to_shared(smem + PIPE_OFF)
        + (unsigned)(jgrp * 4096 + wk * 512 + lane * 16);
    const char* pipe_rd = smem + PIPE_OFF + jgrp * 4096 + wk * 512 + lane * 16;

    scls[tid]       = (target[tid] >= -0.5f) ? 1 : 0;
    scls[tid + 256] = (target[tid + 256] >= -0.5f) ? 1 : 0;
    if (blockIdx.x == 0 && tid == 0) out[0] = 0.f;
    __syncthreads();

    const float w1q0 = (float)scls[kb],     w1q1 = (float)scls[kb + 1];
    const float w1q2 = (float)scls[kb + 2], w1q3 = (float)scls[kb + 3];

    const int t0r = (int)((long long)blockIdx.x * NTILE / GRID);
    const int t1r = (int)((long long)(blockIdx.x + 1) * NTILE / GRID);
    const int G   = (t1r - t0r) * 4;   // row-groups: one i, 4 j, 8KB each

    // per-thread self-consumed cp.async: this thread's 2 rows x 16B
#define ISSUE(gi) { \
    int gg = (gi) < G ? (gi) : (G - 1); \
    int tt = t0r + (gg >> 2); \
    int ii = ((tt & 127) << 2) + (gg & 3); \
    int jb = (tt >> 7) * 4 + jgrp * 2; \
    const float* a = x + ((size_t)ii << 18) + ((size_t)jb << 9) + kb; \
    unsigned d = pipe_wr + ((gg & 1) << 13); \
    cpa16(d,        a); \
    cpa16(d + 2048, a + 512); \
    asm volatile("cp.async.commit_group;"); }

    ISSUE(0)
    ISSUE(1)

    ull a0[8];
#pragma unroll
    for (int q = 0; q < 8; q++) a0[q] = 0ull;
    int curjt = t0r >> 7;
    int jq = curjt * 4 + jgrp * 2;   // warp's first j
    int cj0 = scls[jq], cj1 = scls[jq + 1];

    for (int g = 0; g < G; g++) {
        const int tt = t0r + (g >> 2);
        if ((g & 3) == 0) {
            const int jt = tt >> 7;
            if (jt != curjt) {   // flush F0 for finished j-tile
                float4* f0p = reinterpret_cast<float4*>(gF0);
#pragma unroll
                for (int jj = 0; jj < 2; jj++) {
                    float4* p = f0p + ((((size_t)(jq + jj)) << 9) + kb) / 2;
                    redAdd4(p,     lo2(a0[jj*4+0]), hi2(a0[jj*4+0]),
                                   lo2(a0[jj*4+1]), hi2(a0[jj*4+1]));
                    redAdd4(p + 1, lo2(a0[jj*4+2]), hi2(a0[jj*4+2]),
                                   lo2(a0[jj*4+3]), hi2(a0[jj*4+3]));
                }
#pragma unroll
                for (int q = 0; q < 8; q++) a0[q] = 0ull;
                curjt = jt;
                jq = jt * 4 + jgrp * 2;
                cj0 = scls[jq]; cj1 = scls[jq + 1];
            }
        }
        const int i  = ((tt & 127) << 2) + (g & 3);
        const int ci = scls[i];
        const int s  = g & 1;

        asm volatile("cp.async.wait_group 1;" ::: "memory");
        const char* rp = pipe_rd + (s << 13);
        float4 v0 = *reinterpret_cast<const float4*>(rp);
        float4 v1 = *reinterpret_cast<const float4*>(rp + 2048);

        ISSUE(g + 2)

        ull f1q0 = 0ull, f1q1 = 0ull, f1q2 = 0ull, f1q3 = 0ull;
        float vv[4];   // 0:E(j0) 1:E(j1) 2:S(j0) 3:S(j1)
        ROW(v0, cj0, 0)
        ROW(v1, cj1, 1)

        // F2: 4-value packed butterfly over this warp's 128 k
        {
            bool hi16 = (lane & 16) != 0;
#pragma unroll
            for (int r = 0; r < 2; r++) {
                float send = hi16 ? vv[r] : vv[2 + r];
                float keep = hi16 ? vv[2 + r] : vv[r];
                vv[r] = keep + __shfl_xor_sync(FULL, send, 16);
            }
            bool hi8 = (lane & 8) != 0;
            {
                float send = hi8 ? vv[0] : vv[1];
                float keep = hi8 ? vv[1] : vv[0];
                vv[0] = keep + __shfl_xor_sync(FULL, send, 8);
            }
            vv[0] += __shfl_xor_sync(FULL, vv[0], 4);
            vv[0] += __shfl_xor_sync(FULL, vv[0], 2);
            vv[0] += __shfl_xor_sync(FULL, vv[0], 1);
            if ((lane & 7) == 0) {
                int r  = (lane >> 3) & 1;   // j offset
                int es = lane >> 4;         // 0=E, 1=S
                atomicAdd(reinterpret_cast<float*>(gF2)
                              + ((((size_t)i) << 9) + jq + r) * 2 + es,
                          vv[0]);           // 4 consecutive floats -> 1 sector
            }
        }

        // stage F1 ({E,S} per k, summed over warp's 2 j); buffer = pair parity
        {
            ull* sp = sF1 + (size_t)((g >> 1) & 1) * 2048
                          + (size_t)(s * 2 + jgrp) * 512 + wk * 32 + lane;
            sp[0]   = f1q0;
            sp[128] = f1q1;
            sp[256] = f1q2;
            sp[384] = f1q3;
        }

        if (s) {   // end of a 2-row pair: gather + red.v4
            __syncthreads();
            const ull* buf = sF1 + (size_t)((g >> 1) & 1) * 2048;
            const int il_p = tid >> 7;
            const int k4   = (tid & 127) * 4;
            const ull* s0p = buf + (size_t)(il_p * 2) * 512
                                 + (k4 >> 7) * 32 + ((k4 >> 2) & 31);
            const ull* s1p = s0p + 512;
            ull q0 = s0p[0],   q1 = s0p[128], q2 = s0p[256], q3 = s0p[384];
            fadd2(q0, s1p[0]);   fadd2(q1, s1p[128]);
            fadd2(q2, s1p[256]); fadd2(q3, s1p[384]);
            const int ig = ((tt & 127) << 2) + (g & 3) - 1 + il_p;
            float4* p = reinterpret_cast<float4*>(gF1)
                        + ((((size_t)ig) << 9) + k4) / 2;
            redAdd4(p,     lo2(q0), hi2(q0), lo2(q1), hi2(q1));
            redAdd4(p + 1, lo2(q2), hi2(q2), lo2(q3), hi2(q3));
        }
    }

    // final F0 flush
    {
        float4* f0p = reinterpret_cast<float4*>(gF0);
#pragma unroll
        for (int jj = 0; jj < 2; jj++) {
            float4* p = f0p + ((((size_t)(jq + jj)) << 9) + kb) / 2;
            redAdd4(p,     lo2(a0[jj*4+0]), hi2(a0[jj*4+0]),
                           lo2(a0[jj*4+1]), hi2(a0[jj*4+1]));
            redAdd4(p + 1, lo2(a0[jj*4+2]), hi2(a0[jj*4+2]),
                           lo2(a0[jj*4+3]), hi2(a0[jj*4+3]));
        }
    }
}

__global__ void finalize_kernel(const float* __restrict__ target,
                                float* __restrict__ out) {
    const int tidx = threadIdx.x;                 // 256 threads, 512 blocks
    const unsigned FULL = 0xffffffffu;
    __shared__ int scls2[BB];
    __shared__ int sN1;
    const int b0v = (target[tidx] >= -0.5f) ? 1 : 0;
    const int b1v = (target[tidx + 256] >= -0.5f) ? 1 : 0;
    scls2[tidx]       = b0v;
    scls2[tidx + 256] = b1v;
    if (tidx == 0) sN1 = 0;
    __syncthreads();
    {
        int my = b0v + b1v;
#pragma unroll
        for (int o = 16; o > 0; o >>= 1) my += __shfl_xor_sync(FULL, my, o);
        if ((tidx & 31) == 0) atomicAdd(&sN1, my);
    }
    __syncthreads();
    const int n1 = sN1;

    const size_t t4 = (size_t)blockIdx.x * 256 + tidx;  // float4 slot = 2 {E,S} slots
    const int a  = (int)(t4 >> 8);
    const int b0 = (int)((t4 & 255) * 2);

    float4 f0 = gF0[t4], f1 = gF1[t4], f2 = gF2[t4];
    float4 z = make_float4(0.f, 0.f, 0.f, 0.f);
    gF0[t4] = z; gF1[t4] = z; gF2[t4] = z;   // self-zero for next launch

    const int ca = scls2[a];
    const float n   = (float)(ca ? n1 : (BB - n1));
    const float inv = 1.0f / n;
    float c = 0.f;
    if (ca == scls2[b0])
        c += __logf(f0.x) + __logf(f1.x) + __logf(f2.x)
             - (f0.y + f1.y + f2.y) * inv;
    if (ca == scls2[b0 + 1])
        c += __logf(f0.z) + __logf(f1.z) + __logf(f2.z)
             - (f0.w + f1.w + f2.w) * inv;
    c *= (1.0f / (float)(BB * BB));
#pragma unroll
    for (int o = 16; o > 0; o >>= 1) c += __shfl_xor_sync(FULL, c, o);
    __shared__ float sacc[8];
    if ((tidx & 31) == 0) sacc[tidx >> 5] = c;
    __syncthreads();
    if (tidx < 8) {
        float vsum = sacc[tidx];
#pragma unroll
        for (int o = 4; o > 0; o >>= 1) vsum += __shfl_xor_sync(0xffu, vsum, o);
        if (tidx == 0) atomicAdd(out, vsum);
    }
}

extern "C" void kernel_launch(void* const* d_in, const int* in_sizes, int n_in,
                              void* d_out, int out_size) {
    const float* cube   = (const float*)d_in[0];
    const float* target = (const float*)d_in[1];
    if (n_in >= 2 && in_sizes[0] < in_sizes[1]) {  // defensive order check
        cube   = (const float*)d_in[1];
        target = (const float*)d_in[0];
    }
    float* out = (float*)d_out;

    static bool attr_set = false;
    if (!attr_set) {
        cudaFuncSetAttribute(main_kernel,
                             cudaFuncAttributeMaxDynamicSharedMemorySize, SMEM_BYTES);
        attr_set = true;
    }

    main_kernel<<<GRID, NT, SMEM_BYTES>>>(cube, target, out);
    finalize_kernel<<<BB * BB / 512, 256>>>(target, out);
}

// round 17
// speedup vs baseline: 1.2477x; 1.2477x over previous
#include <cuda_runtime.h>
#include <cstdint>
#include <cstddef>

#define BB 512
#define NT 256
#define GRID 456      // 3 blocks/SM x 152 SMs, single wave
#define NTILE 8192    // 64 j-tiles (8 j) x 128 i-splits (4 i)
// smem: [0,2048) classes | [2048, 34816) F1 staging 32KB | [34816, 67584) cp.async pipe 32KB
#define STG_OFF 2048
#define PIPE_OFF 34816
#define SMEM_BYTES 67584

typedef unsigned long long ull;

// Face accumulators {E,S}; .bss zero at load, finalize re-zeroes after reading.
__device__ float4 gF0[BB * BB / 2];  // [j*B+k]: sum over i
__device__ float4 gF1[BB * BB / 2];  // [i*B+k]: sum over j
__device__ float4 gF2[BB * BB / 2];  // [i*B+j]: sum over k

__device__ __forceinline__ void redAdd4(float4* p, float a, float b, float c, float d) {
    asm volatile("red.global.add.v4.f32 [%0], {%1, %2, %3, %4};"
                 :: "l"(p), "f"(a), "f"(b), "f"(c), "f"(d));
}
__device__ __forceinline__ ull pk2(float lo, float hi) {
    ull r; asm("mov.b64 %0, {%1, %2};" : "=l"(r) : "f"(lo), "f"(hi)); return r;
}
__device__ __forceinline__ void fadd2(ull& a, ull b) {
    asm("add.rn.f32x2 %0, %0, %1;" : "+l"(a) : "l"(b));
}
__device__ __forceinline__ float lo2(ull a) {
    float f; asm("{.reg .f32 h; mov.b64 {%0, h}, %1;}" : "=f"(f) : "l"(a)); return f;
}
__device__ __forceinline__ float hi2(ull a) {
    float f; asm("{.reg .f32 l; mov.b64 {l, %0}, %1;}" : "=f"(f) : "l"(a)); return f;
}
__device__ __forceinline__ void cpa16(unsigned dst, const void* src) {
    asm volatile("cp.async.cg.shared.global [%0], [%1], 16;"
                 :: "r"(dst), "l"(src));
}

#define ROW(vq, cjv, jj) { \
    const float fij = ((cjv) == ci) ? 1.f : 0.f; \
    float e0 = __expf(vq.x), e1 = __expf(vq.y), e2 = __expf(vq.z), e3 = __expf(vq.w); \
    ull t0 = pk2(e0, fij * vq.x), t1 = pk2(e1, fij * vq.y); \
    ull t2 = pk2(e2, fij * vq.z), t3 = pk2(e3, fij * vq.w); \
    fadd2(a0[(jj)*4+0], t0); fadd2(a0[(jj)*4+1], t1); \
    fadd2(a0[(jj)*4+2], t2); fadd2(a0[(jj)*4+3], t3); \
    fadd2(f1q0, t0); fadd2(f1q1, t1); fadd2(f1q2, t2); fadd2(f1q3, t3); \
    float sv  = (vq.x + vq.y) + (vq.z + vq.w); \
    float rs1 = vq.x * w1q0 + vq.y * w1q1 + vq.z * w1q2 + vq.w * w1q3; \
    vv[4 + (jj)] = ci ? rs1 : (sv - rs1); \
    vv[(jj)] = (e0 + e1) + (e2 + e3); }

__global__ __launch_bounds__(NT, 3) void main_kernel(const float* __restrict__ x,
                                                     const float* __restrict__ target,
                                                     float* __restrict__ out) {
    const int tid  = threadIdx.x;
    const int lane = tid & 31;
    const int w    = tid >> 5;       // 0..7
    const int quad = w >> 2;         // 0..1
    const int wk   = w & 3;          // 0..3
    const int kb   = wk * 128 + lane * 4;
    const unsigned FULL = 0xffffffffu;

    extern __shared__ char smem[];
    int* scls = reinterpret_cast<int*>(smem);
    ull* sF1  = reinterpret_cast<ull*>(smem + STG_OFF);
    const unsigned pipe_u32 =
        (unsigned)__cvta_generic_to_shared(smem + PIPE_OFF) + tid * 16;
    const float4* vpipe = reinterpret_cast<const float4*>(smem + PIPE_OFF) + tid;

    scls[tid]       = (target[tid] >= -0.5f) ? 1 : 0;
    scls[tid + 256] = (target[tid + 256] >= -0.5f) ? 1 : 0;
    if (blockIdx.x == 0 && tid == 0) out[0] = 0.f;
    __syncthreads();

    const float w1q0 = (float)scls[kb],     w1q1 = (float)scls[kb + 1];
    const float w1q2 = (float)scls[kb + 2], w1q3 = (float)scls[kb + 3];

    const int t0r = (int)((long long)blockIdx.x * NTILE / GRID);
    const int t1r = (int)((long long)(blockIdx.x + 1) * NTILE / GRID);
    const int G   = (t1r - t0r) * 4;   // row-groups (one i each)

#define ISSUE(gi) { \
    int gg = (gi) < G ? (gi) : (G - 1); \
    int tt = t0r + (gg >> 2); \
    int ii = ((tt & 127) << 2) + (gg & 3); \
    int jb = (tt >> 7) * 8 + quad * 4; \
    const float* a = x + ((size_t)ii << 18) + ((size_t)jb << 9) + kb; \
    unsigned d = pipe_u32 + ((gg & 1) << 14); \
    cpa16(d,         a); \
    cpa16(d + 4096,  a + 512); \
    cpa16(d + 8192,  a + 1024); \
    cpa16(d + 12288, a + 1536); \
    asm volatile("cp.async.commit_group;"); }

    ISSUE(0)
    ISSUE(1)

    ull a0[16];
#pragma unroll
    for (int q = 0; q < 16; q++) a0[q] = 0ull;
    int curjt = t0r >> 7;
    int jbase = curjt * 8 + quad * 4;
    int cj0 = scls[jbase],     cj1 = scls[jbase + 1];
    int cj2 = scls[jbase + 2], cj3 = scls[jbase + 3];

    for (int g = 0; g < G; g++) {
        const int tt = t0r + (g >> 2);
        if ((g & 3) == 0) {
            const int jt = tt >> 7;
            if (jt != curjt) {   // flush F0 for finished j-tile
                float4* f0p = reinterpret_cast<float4*>(gF0);
#pragma unroll
                for (int jj = 0; jj < 4; jj++) {
                    float4* p = f0p + ((((size_t)(jbase + jj)) << 9) + kb) / 2;
                    redAdd4(p,     lo2(a0[jj*4+0]), hi2(a0[jj*4+0]),
                                   lo2(a0[jj*4+1]), hi2(a0[jj*4+1]));
                    redAdd4(p + 1, lo2(a0[jj*4+2]), hi2(a0[jj*4+2]),
                                   lo2(a0[jj*4+3]), hi2(a0[jj*4+3]));
                }
#pragma unroll
                for (int q = 0; q < 16; q++) a0[q] = 0ull;
                curjt = jt;
                jbase = jt * 8 + quad * 4;
                cj0 = scls[jbase];     cj1 = scls[jbase + 1];
                cj2 = scls[jbase + 2]; cj3 = scls[jbase + 3];
            }
        }
        const int i  = ((tt & 127) << 2) + (g & 3);
        const int ci = scls[i];

        asm volatile("cp.async.wait_group 1;" ::: "memory");
        const float4* vp = vpipe + ((size_t)(g & 1) << 10);  // stage = 1024 float4
        float4 v0 = vp[0];
        float4 v1 = vp[256];
        float4 v2 = vp[512];
        float4 v3 = vp[768];

        ISSUE(g + 2)

        ull f1q0 = 0ull, f1q1 = 0ull, f1q2 = 0ull, f1q3 = 0ull;
        float vv[8];
        ROW(v0, cj0, 0)
        ROW(v1, cj1, 1)
        ROW(v2, cj2, 2)
        ROW(v3, cj3, 3)

        // F2: batched 8-value butterfly (4 j x {E,S}) over this warp's 128 k
        {
            bool hi16 = (lane & 16) != 0;
#pragma unroll
            for (int r = 0; r < 4; r++) {
                float send = hi16 ? vv[r] : vv[4 + r];
                float keep = hi16 ? vv[4 + r] : vv[r];
                vv[r] = keep + __shfl_xor_sync(FULL, send, 16);
            }
            bool hi8 = (lane & 8) != 0;
            {
                float s0 = hi8 ? vv[0] : vv[2];
                float k0v = hi8 ? vv[2] : vv[0];
                vv[0] = k0v + __shfl_xor_sync(FULL, s0, 8);
                float s1 = hi8 ? vv[1] : vv[3];
                float k1v = hi8 ? vv[3] : vv[1];
                vv[1] = k1v + __shfl_xor_sync(FULL, s1, 8);
            }
            bool hi4 = (lane & 4) != 0;
            {
                float s0 = hi4 ? vv[0] : vv[1];
                float k0v = hi4 ? vv[1] : vv[0];
                vv[0] = k0v + __shfl_xor_sync(FULL, s0, 4);
            }
            vv[0] += __shfl_xor_sync(FULL, vv[0], 2);
            vv[0] += __shfl_xor_sync(FULL, vv[0], 1);
            if ((lane & 3) == 0) {
                int r  = ((lane >> 3) & 1) * 2 + ((lane >> 2) & 1);
                int es = (lane >> 4) & 1;
                atomicAdd(reinterpret_cast<float*>(gF2)
                              + ((((size_t)i) << 9) + jbase + r) * 2 + es,
                          vv[0]);
            }
        }

        // stage F1 ({E,S} per k, summed over warp's 4 j); buffer = pair parity
        {
            ull* sp = sF1 + (size_t)((g >> 1) & 1) * 2048
                          + (size_t)((g & 1) * 2 + quad) * 512 + wk * 32 + lane;
            sp[0]   = f1q0;
            sp[128] = f1q1;
            sp[256] = f1q2;
            sp[384] = f1q3;
        }

        if (g & 1) {   // end of a 2-row pair: gather + red.v4
            __syncthreads();
            const ull* buf = sF1 + (size_t)((g >> 1) & 1) * 2048;
            const int il_p = tid >> 7;
            const int k4   = (tid & 127) * 4;
            const ull* s0p = buf + (size_t)(il_p * 2) * 512
                                 + (k4 >> 7) * 32 + ((k4 >> 2) & 31);
            const ull* s1p = s0p + 512;
            ull q0 = s0p[0],   q1 = s0p[128], q2 = s0p[256], q3 = s0p[384];
            fadd2(q0, s1p[0]);   fadd2(q1, s1p[128]);
            fadd2(q2, s1p[256]); fadd2(q3, s1p[384]);
            const int ig = ((tt & 127) << 2) + (g & 3) - 1 + il_p;
            float4* p = reinterpret_cast<float4*>(gF1)
                        + ((((size_t)ig) << 9) + k4) / 2;
            redAdd4(p,     lo2(q0), hi2(q0), lo2(q1), hi2(q1));
            redAdd4(p + 1, lo2(q2), hi2(q2), lo2(q3), hi2(q3));
        }
    }

    // final F0 flush
    {
        float4* f0p = reinterpret_cast<float4*>(gF0);
#pragma unroll
        for (int jj = 0; jj < 4; jj++) {
            float4* p = f0p + ((((size_t)(jbase + jj)) << 9) + kb) / 2;
            redAdd4(p,     lo2(a0[jj*4+0]), hi2(a0[jj*4+0]),
                           lo2(a0[jj*4+1]), hi2(a0[jj*4+1]));
            redAdd4(p + 1, lo2(a0[jj*4+2]), hi2(a0[jj*4+2]),
                           lo2(a0[jj*4+3]), hi2(a0[jj*4+3]));
        }
    }
}

// finalize v3: 128 blocks x 512 threads, 2 float4 slots per thread, MLP-6 loads
__global__ __launch_bounds__(512) void finalize_kernel(const float* __restrict__ target,
                                                       float* __restrict__ out) {
    const int tidx = threadIdx.x;                 // 512 threads, 128 blocks
    const unsigned FULL = 0xffffffffu;
    __shared__ int scls2[BB];
    const int cb_own = (target[tidx] >= -0.5f) ? 1 : 0;
    scls2[tidx] = cb_own;
    const int n1 = __syncthreads_count(cb_own);

    const float invP = 1.0f / (float)n1;
    const float invN = 1.0f / (float)(BB - n1);

    const size_t tA = (size_t)blockIdx.x * 512 + tidx;   // slots [0, 65536)
    const size_t tB = tA + 65536;                        // slots [65536, 131072)

    // issue all 6 loads before any use (MLP 6)
    float4 fa0 = gF0[tA], fa1 = gF1[tA], fa2 = gF2[tA];
    float4 fb0 = gF0[tB], fb1 = gF1[tB], fb2 = gF2[tB];
    float4 z = make_float4(0.f, 0.f, 0.f, 0.f);
    gF0[tA] = z; gF1[tA] = z; gF2[tA] = z;   // self-zero for next launch
    gF0[tB] = z; gF1[tB] = z; gF2[tB] = z;

    float c = 0.f;
    {
        const int a  = (int)(tA >> 8);
        const int b0 = (int)((tA & 255) * 2);
        const int ca = scls2[a];
        const float inv = ca ? invP : invN;
        if (ca == scls2[b0])
            c += __logf(fa0.x) + __logf(fa1.x) + __logf(fa2.x)
                 - (fa0.y + fa1.y + fa2.y) * inv;
        if (ca == scls2[b0 + 1])
            c += __logf(fa0.z) + __logf(fa1.z) + __logf(fa2.z)
                 - (fa0.w + fa1.w + fa2.w) * inv;
    }
    {
        const int a  = (int)(tB >> 8);
        const int b0 = (int)((tB & 255) * 2);
        const int ca = scls2[a];
        const float inv = ca ? invP : invN;
        if (ca == scls2[b0])
            c += __logf(fb0.x) + __logf(fb1.x) + __logf(fb2.x)
                 - (fb0.y + fb1.y + fb2.y) * inv;
        if (ca == scls2[b0 + 1])
            c += __logf(fb0.z) + __logf(fb1.z) + __logf(fb2.z)
                 - (fb0.w + fb1.w + fb2.w) * inv;
    }
    c *= (1.0f / (float)(BB * BB));
#pragma unroll
    for (int o = 16; o > 0; o >>= 1) c += __shfl_xor_sync(FULL, c, o);
    __shared__ float sacc[16];
    if ((tidx & 31) == 0) sacc[tidx >> 5] = c;
    __syncthreads();
    if (tidx < 16) {
        float vsum = sacc[tidx];
#pragma unroll
        for (int o = 8; o > 0; o >>= 1) vsum += __shfl_xor_sync(0xffffu, vsum, o);
        if (tidx == 0) atomicAdd(out, vsum);
    }
}

extern "C" void kernel_launch(void* const* d_in, const int* in_sizes, int n_in,
                              void* d_out, int out_size) {
    const float* cube   = (const float*)d_in[0];
    const float* target = (const float*)d_in[1];
    if (n_in >= 2 && in_sizes[0] < in_sizes[1]) {  // defensive order check
        cube   = (const float*)d_in[1];
        target = (const float*)d_in[0];
    }
    float* out = (float*)d_out;

    static bool attr_set = false;
    if (!attr_set) {
        cudaFuncSetAttribute(main_kernel,
                             cudaFuncAttributeMaxDynamicSharedMemorySize, SMEM_BYTES);
        attr_set = true;
    }

    main_kernel<<<GRID, NT, SMEM_BYTES>>>(cube, target, out);
    finalize_kernel<<<128, 512>>>(target, out);
}